// round 14
// baseline (speedup 1.0000x reference)
#include <cuda_runtime.h>

// EthanolSNN: 3-layer LIF SNN inference. T=256, B=8192, D=64, H1=28, H2=14.
// Output mem3 [T, B, 1] fp32.
//
// Two-kernel split:
//  K1 (r13): layer-1 accumulations, 2 element-timesteps per thread,
//      128 threads/block (r12 used 64 -> only 1.5 warps/SMSP resident; all
//      prior K1 variants were exposed-latency-bound at ~344us). Same smem
//      footprint -> 3 blocks/SM -> 3 warps/SMSP now.
//  K2: sequential LIF recurrence with register double-buffered acc loads
//      (UNCHANGED from r11, measured 133-144us).
//  Dummy launches reorder the ncu -s5 -c1 capture window onto K1.
//
// Numerics BIT-IDENTICAL to round-5 passing kernel (rel_err 7.44e-4):
//  - dot products: single serial ascending-index FMA chain per neuron
//  - bias added as separate rounded add after the chain
//  - LIF: RN(RN(RN(b*m)+cur)-reset), reset subtract via exact-product fma
//  - threshold m>1 == (m-1)>0 in fp32

typedef unsigned long long ull_t;

#define TT 256
#define BB 8192
#define DD 64
#define HH1 28
#define HH2 14

// scratch: [et][16] ull; et = t*BB+e; half q uses slots [q*8 .. q*8+6]
#define SCRATCH_ULLS (256ULL * 8192ULL * 16ULL)
__device__ ull_t g_cur1[SCRATCH_ULLS];   // 268 MB, module-load allocated

__device__ __forceinline__ ull_t pk2(float lo, float hi) {
    ull_t r;
    asm("mov.b64 %0, {%1, %2};" : "=l"(r) : "f"(lo), "f"(hi));
    return r;
}
__device__ __forceinline__ void upk2(ull_t v, float& lo, float& hi) {
    asm("mov.b64 {%0, %1}, %2;" : "=f"(lo), "=f"(hi) : "l"(v));
}
__device__ __forceinline__ ull_t fma2(ull_t a, ull_t b, ull_t c) {
    ull_t d;
    asm("fma.rn.f32x2 %0, %1, %2, %3;" : "=l"(d) : "l"(a), "l"(b), "l"(c));
    return d;
}
__device__ __forceinline__ ull_t add2(ull_t a, ull_t b) {
    ull_t d;
    asm("add.rn.f32x2 %0, %1, %2;" : "=l"(d) : "l"(a), "l"(b));
    return d;
}
__device__ __forceinline__ ull_t mul2(ull_t a, ull_t b) {
    ull_t d;
    asm("mul.rn.f32x2 %0, %1, %2;" : "=l"(d) : "l"(a), "l"(b));
    return d;
}

// Dummy kernel: shifts the ncu -s5 -c1 capture window so launch #6 is K1.
__global__ void snn_nop_kernel() {}

// ============================================================================
// Kernel 1 (r13): layer-1 accumulation, 2 element-timesteps per thread,
// 128 threads/block (3 blocks/SM -> 3 warps/SMSP resident).
//  - block covers 256 consecutive et; thread tid owns rows tid, tid+128
//  - stage loads: fully coalesced LDG.128 into smem (rows stride 65 floats)
//  - per k: 7 weight LDS.128 (warp-uniform broadcast) reused for 2 elements
//  - compute LDS.32 x reads: bank (tid+k)%32, conflict-free
// 2 x 14 serial ascending-k fma2 chains (bit-identical numerics).
// ============================================================================
__global__ void __launch_bounds__(128)
snn_layer1_kernel(const float* __restrict__ x, const float* __restrict__ W1)
{
    __shared__ __align__(16) ull_t w1p[DD * 16];   // [k][16]: pairs j=0..13, pad (8KB)
    __shared__ float xs[256 * 65];                 // 256 rows, stride 65 (66.6KB)

    const int tid = threadIdx.x;   // 0..127

    // ---- pack W1 pairs: w1p[k*16+j] = {W1[2j][k], W1[2j+1][k]} ----
    for (int idx = tid; idx < DD * 16; idx += 128) {
        int k = idx >> 4, j = idx & 15;
        float lo = 0.f, hi = 0.f;
        if (j < 14) {
            lo = W1[(2 * j)     * DD + k];
            hi = W1[(2 * j + 1) * DD + k];
        }
        w1p[idx] = pk2(lo, hi);
    }

    // ---- stage this block's 256 x rows (contiguous 64KB of x) ----
    const float4* xg = (const float4*)(x + (size_t)blockIdx.x * (256 * DD));
    #pragma unroll
    for (int r = 0; r < 32; r++) {
        int pos = tid + 128 * r;            // float4 index within 4096-float4 tile
        float4 v = __ldcs(xg + pos);
        int row = pos >> 4;                 // 0..255
        int col = (pos & 15) * 4;           // 0..60
        float* dst = &xs[row * 65 + col];
        dst[0] = v.x; dst[1] = v.y; dst[2] = v.z; dst[3] = v.w;
    }
    __syncthreads();

    // ---- 2 x 14 serial ascending-k fma2 chains ----
    ull_t acc[2][14];
    #pragma unroll
    for (int u = 0; u < 2; u++)
        #pragma unroll
        for (int j = 0; j < 14; j++) acc[u][j] = 0ULL;

    #pragma unroll 1
    for (int k = 0; k < DD; k++) {
        const ulonglong2* wr = (const ulonglong2*)(w1p + k * 16);
        ulonglong2 w01 = wr[0], w23 = wr[1], w45 = wr[2], w67 = wr[3],
                   w89 = wr[4], wab = wr[5], wcd = wr[6];
        #pragma unroll
        for (int u = 0; u < 2; u++) {
            float xv = xs[(tid + 128 * u) * 65 + k];
            ull_t xx = pk2(xv, xv);
            acc[u][0]  = fma2(xx, w01.x, acc[u][0]);
            acc[u][1]  = fma2(xx, w01.y, acc[u][1]);
            acc[u][2]  = fma2(xx, w23.x, acc[u][2]);
            acc[u][3]  = fma2(xx, w23.y, acc[u][3]);
            acc[u][4]  = fma2(xx, w45.x, acc[u][4]);
            acc[u][5]  = fma2(xx, w45.y, acc[u][5]);
            acc[u][6]  = fma2(xx, w67.x, acc[u][6]);
            acc[u][7]  = fma2(xx, w67.y, acc[u][7]);
            acc[u][8]  = fma2(xx, w89.x, acc[u][8]);
            acc[u][9]  = fma2(xx, w89.y, acc[u][9]);
            acc[u][10] = fma2(xx, wab.x, acc[u][10]);
            acc[u][11] = fma2(xx, wab.y, acc[u][11]);
            acc[u][12] = fma2(xx, wcd.x, acc[u][12]);
            acc[u][13] = fma2(xx, wcd.y, acc[u][13]);
        }
    }

    // ---- store to scratch [et][16]: slots 0..6 = pairs 0..6 (q=0 half),
    //      slots 8..14 = pairs 7..13 (q=1 half); aligned STG.128 ----
    #pragma unroll
    for (int u = 0; u < 2; u++) {
        const size_t et = (size_t)blockIdx.x * 256 + tid + 128 * u;
        ulonglong2* d = (ulonglong2*)(g_cur1 + et * 16);
        ulonglong2 p;
        p.x = acc[u][0];  p.y = acc[u][1];  d[0] = p;
        p.x = acc[u][2];  p.y = acc[u][3];  d[1] = p;
        p.x = acc[u][4];  p.y = acc[u][5];  d[2] = p;
        p.x = acc[u][6];  p.y = 0ULL;       d[3] = p;
        p.x = acc[u][7];  p.y = acc[u][8];  d[4] = p;
        p.x = acc[u][9];  p.y = acc[u][10]; d[5] = p;
        p.x = acc[u][11]; p.y = acc[u][12]; d[6] = p;
        p.x = acc[u][13]; p.y = 0ULL;       d[7] = p;
    }
}

// ============================================================================
// Kernel 2: LIF recurrence (r11, UNCHANGED — measured 133-144us).
// ============================================================================
__global__ void __launch_bounds__(64, 1)
snn_recur_kernel(const float* __restrict__ b1,
                 const float* __restrict__ W2, const float* __restrict__ b2,
                 const float* __restrict__ W3, const float* __restrict__ b3,
                 float* __restrict__ out)
{
    __shared__ __align__(16) ull_t w2p[HH1 * 8];
    __shared__ ull_t b1p[14];
    __shared__ ull_t b2p[8];
    __shared__ float w3s[14];
    __shared__ float b3s;

    const int tid  = threadIdx.x;
    const int lane = tid & 31;
    const int warp = tid >> 5;
    const int p    = lane >> 1;            // element slot within warp (0..15)
    const int q    = lane & 1;             // neuron-half owner
    const int e    = blockIdx.x * 32 + warp * 16 + p;

    for (int idx = tid; idx < HH1 * 8; idx += 64) {
        int i = idx >> 3, r = idx & 7, qq = r >> 2, m = r & 3;
        float lo = (2 * m     < 7) ? W2[(qq * 7 + 2 * m)     * HH1 + i] : 0.f;
        float hi = (2 * m + 1 < 7) ? W2[(qq * 7 + 2 * m + 1) * HH1 + i] : 0.f;
        w2p[idx] = pk2(lo, hi);
    }
    if (tid < 14) {
        int qq = tid / 7, ii = tid - qq * 7;
        b1p[tid] = pk2(b1[qq * 14 + 2 * ii], b1[qq * 14 + 2 * ii + 1]);
        w3s[tid] = W3[tid];
    }
    if (tid < 8) {
        int qq = tid >> 2, m = tid & 3;
        float lo = (2 * m     < 7) ? b2[qq * 7 + 2 * m]     : 0.f;
        float hi = (2 * m + 1 < 7) ? b2[qq * 7 + 2 * m + 1] : 0.f;
        b2p[tid] = pk2(lo, hi);
    }
    if (tid == 0) b3s = b3[0];
    __syncthreads();

    ull_t b1own[7], b2own[4];
    #pragma unroll
    for (int i = 0; i < 7; i++) b1own[i] = b1p[q * 7 + i];
    #pragma unroll
    for (int m = 0; m < 4; m++) b2own[m] = b2p[q * 4 + m];

    const ull_t BETA2 = pk2(0.9f, 0.9f);
    const ull_t NEG2  = pk2(-1.0f, -1.0f);

    ull_t m1v[7], m2v[4];
    #pragma unroll
    for (int i = 0; i < 7; i++) m1v[i] = 0ULL;
    #pragma unroll
    for (int m = 0; m < 4; m++) m2v[m] = 0ULL;
    float m3 = 0.0f;

    const ull_t* cbase = g_cur1 + (size_t)e * 16 + q * 8;
    const size_t cstep = (size_t)BB * 16;

    // ---- preload acc for t=0 ----
    ulonglong2 c0, c1, c2, c3v;
    {
        const ulonglong2* cp = (const ulonglong2*)cbase;
        c0 = cp[0]; c1 = cp[1]; c2 = cp[2]; c3v = cp[3];
    }

    #pragma unroll 1
    for (int t = 0; t < TT; t++) {
        // ---- issue next step's acc loads NOW (consumed next iteration) ----
        const int tn = (t + 1 < TT) ? (t + 1) : t;
        const ulonglong2* np = (const ulonglong2*)(cbase + (size_t)tn * cstep);
        ulonglong2 n0 = np[0], n1 = np[1], n2 = np[2], n3 = np[3];

        // ---- prefetch t+2 into L2 so next iteration's LDG is an L2 hit ----
        if (t + 2 < TT) {
            const char* pf = (const char*)(cbase + (size_t)(t + 2) * cstep);
            asm volatile("prefetch.global.L2 [%0];" :: "l"(pf));
        }

        ull_t acc[7] = {c0.x, c0.y, c1.x, c1.y, c2.x, c2.y, c3v.x};

        // ---- LIF layer 1 (exact rounding sequence) ----
        float s1own[14];
        #pragma unroll
        for (int i = 0; i < 7; i++) {
            ull_t mold = m1v[i];
            float mlo, mhi;
            upk2(mold, mlo, mhi);
            float rlo = (mlo > 1.0f) ? 1.0f : 0.0f;
            float rhi = (mhi > 1.0f) ? 1.0f : 0.0f;
            ull_t cur = add2(acc[i], b1own[i]);
            ull_t mb  = mul2(BETA2, mold);
            ull_t tmp = add2(mb, cur);
            ull_t mn  = fma2(pk2(rlo, rhi), NEG2, tmp);
            m1v[i] = mn;
            float nlo, nhi;
            upk2(mn, nlo, nhi);
            s1own[2 * i]     = (nlo > 1.0f) ? 1.0f : 0.0f;
            s1own[2 * i + 1] = (nhi > 1.0f) ? 1.0f : 0.0f;
        }

        // ---- exchange spike halves across the pair ----
        float s1o[14];
        #pragma unroll
        for (int i = 0; i < 7; i++) {
            ull_t sp = pk2(s1own[2 * i], s1own[2 * i + 1]);
            ull_t g  = __shfl_xor_sync(0xFFFFFFFFu, sp, 1);
            upk2(g, s1o[2 * i], s1o[2 * i + 1]);
        }
        float s1all[28];
        #pragma unroll
        for (int i = 0; i < 14; i++) {
            s1all[i]      = q ? s1o[i]   : s1own[i];
            s1all[14 + i] = q ? s1own[i] : s1o[i];
        }

        // ---- layer 2: serial ascending-i FMA chains ----
        ull_t a2[4];
        #pragma unroll
        for (int m = 0; m < 4; m++) a2[m] = 0ULL;
        #pragma unroll
        for (int i = 0; i < HH1; i++) {
            ull_t ss = pk2(s1all[i], s1all[i]);
            const ulonglong2* wr = (const ulonglong2*)(w2p + (size_t)i * 8 + q * 4);
            ulonglong2 u0 = wr[0], u1 = wr[1];
            a2[0] = fma2(ss, u0.x, a2[0]);
            a2[1] = fma2(ss, u0.y, a2[1]);
            a2[2] = fma2(ss, u1.x, a2[2]);
            a2[3] = fma2(ss, u1.y, a2[3]);
        }

        // ---- LIF layer 2 ----
        float s2own[8];
        #pragma unroll
        for (int m = 0; m < 4; m++) {
            ull_t mold = m2v[m];
            float mlo, mhi;
            upk2(mold, mlo, mhi);
            float rlo = (mlo > 1.0f) ? 1.0f : 0.0f;
            float rhi = (mhi > 1.0f) ? 1.0f : 0.0f;
            ull_t cur = add2(a2[m], b2own[m]);
            ull_t mb  = mul2(BETA2, mold);
            ull_t tmp = add2(mb, cur);
            ull_t mn  = fma2(pk2(rlo, rhi), NEG2, tmp);
            m2v[m] = mn;
            float nlo, nhi;
            upk2(mn, nlo, nhi);
            s2own[2 * m]     = (nlo > 1.0f) ? 1.0f : 0.0f;
            s2own[2 * m + 1] = (nhi > 1.0f) ? 1.0f : 0.0f;
        }

        // ---- exchange s2 halves ----
        float s2o[8];
        #pragma unroll
        for (int m = 0; m < 4; m++) {
            ull_t sp = pk2(s2own[2 * m], s2own[2 * m + 1]);
            ull_t g  = __shfl_xor_sync(0xFFFFFFFFu, sp, 1);
            upk2(g, s2o[2 * m], s2o[2 * m + 1]);
        }
        float s2all[14];
        #pragma unroll
        for (int i = 0; i < 7; i++) {
            s2all[i]     = q ? s2o[i]   : s2own[i];
            s2all[7 + i] = q ? s2own[i] : s2o[i];
        }

        // ---- layer 3 + LIF 3 ----
        float c3 = 0.0f;
        #pragma unroll
        for (int i = 0; i < HH2; i++) c3 = fmaf(s2all[i], w3s[i], c3);
        float cur3 = __fadd_rn(c3, b3s);

        float r3  = (m3 > 1.0f) ? 1.0f : 0.0f;
        float mb3 = __fmul_rn(0.9f, m3);
        float t3  = __fadd_rn(mb3, cur3);
        m3 = __fsub_rn(t3, r3);

        if (q == 0) out[(size_t)t * BB + e] = m3;

        // ---- rotate double-buffered acc ----
        c0 = n0; c1 = n1; c2 = n2; c3v = n3;
    }
}

extern "C" void kernel_launch(void* const* d_in, const int* in_sizes, int n_in,
                              void* d_out, int out_size) {
    const float* x  = (const float*)d_in[0];
    const float* W1 = (const float*)d_in[1];
    const float* b1 = (const float*)d_in[2];
    const float* W2 = (const float*)d_in[3];
    const float* b2 = (const float*)d_in[4];
    const float* W3 = (const float*)d_in[5];
    const float* b3 = (const float*)d_in[6];
    float* out = (float*)d_out;

    // Launch pattern period 4: [nop, K1, K2, nop] so ncu -s5 -c1 lands on K1
    // (launch #6 = position 2 of the second call = K1).
    snn_nop_kernel<<<1, 32>>>();

    // K1: 2,097,152 element-timesteps, 2 per thread -> 8192 blocks x 128
    snn_layer1_kernel<<<8192, 128>>>(x, W1);

    // K2: 8192 elements, 32 per block (64 threads = 2 threads per element)
    snn_recur_kernel<<<256, 64>>>(b1, W2, b2, W3, b3, out);

    snn_nop_kernel<<<1, 32>>>();
}

// round 15
// speedup vs baseline: 1.6204x; 1.6204x over previous
#include <cuda_runtime.h>

// EthanolSNN: 3-layer LIF SNN inference. T=256, B=8192, D=64, H1=28, H2=14.
// Output mem3 [T, B, 1] fp32.
//
// Two-kernel split:
//  K1 (r14): layer-1 accumulations, 4 et/thread, 64-thr blocks (r12 skeleton)
//      with k-PACKED weights: one LDS.128 = one neuron-pair x two consecutive
//      k. Plus float4 x loads (one LDS.128 per element per 4 k) from an
//      XOR-swizzled stride-64 smem tile. LDS per warp-k drops 11 -> 4.5,
//      taking the smem crossbar (4cyc/LDS at nw>=4) below the fma2 floor.
//  K2: sequential LIF recurrence with register double-buffered acc loads
//      (UNCHANGED from r11/r12, measured 133-144us).
//
// Numerics BIT-IDENTICAL to round-5 passing kernel (rel_err 7.44e-4):
//  - dot products: single serial ascending-index FMA chain per neuron
//  - bias added as separate rounded add after the chain
//  - LIF: RN(RN(RN(b*m)+cur)-reset), reset subtract via exact-product fma
//  - threshold m>1 == (m-1)>0 in fp32

typedef unsigned long long ull_t;

#define TT 256
#define BB 8192
#define DD 64
#define HH1 28
#define HH2 14

// scratch: [et][16] ull; et = t*BB+e; half q uses slots [q*8 .. q*8+6]
#define SCRATCH_ULLS (256ULL * 8192ULL * 16ULL)
__device__ ull_t g_cur1[SCRATCH_ULLS];   // 268 MB, module-load allocated

__device__ __forceinline__ ull_t pk2(float lo, float hi) {
    ull_t r;
    asm("mov.b64 %0, {%1, %2};" : "=l"(r) : "f"(lo), "f"(hi));
    return r;
}
__device__ __forceinline__ void upk2(ull_t v, float& lo, float& hi) {
    asm("mov.b64 {%0, %1}, %2;" : "=f"(lo), "=f"(hi) : "l"(v));
}
__device__ __forceinline__ ull_t fma2(ull_t a, ull_t b, ull_t c) {
    ull_t d;
    asm("fma.rn.f32x2 %0, %1, %2, %3;" : "=l"(d) : "l"(a), "l"(b), "l"(c));
    return d;
}
__device__ __forceinline__ ull_t add2(ull_t a, ull_t b) {
    ull_t d;
    asm("add.rn.f32x2 %0, %1, %2;" : "=l"(d) : "l"(a), "l"(b));
    return d;
}
__device__ __forceinline__ ull_t mul2(ull_t a, ull_t b) {
    ull_t d;
    asm("mul.rn.f32x2 %0, %1, %2;" : "=l"(d) : "l"(a), "l"(b));
    return d;
}

// ============================================================================
// Kernel 1 (r14): layer-1 accumulation, 4 element-timesteps per thread,
// 64 threads/block (block covers 256 et; thread owns rows tid+64u).
//  - w1t[j*32+kk] (ulonglong2): neuron-pair j, k=2kk and 2kk+1 packed ->
//    7 weight LDS.128 per TWO k per warp (was 7 per one k)
//  - x tile: stride-64 rows, float4 chunks XOR-swizzled by (row&7) ->
//    one x LDS.128 per element per FOUR k, conflict-free all phases
//  - per 4k per warp: 18 LDS + 224 fma2  (r12: 44 LDS + 224 fma2)
// 4 x 14 serial ascending-k fma2 chains (bit-identical numerics).
// ============================================================================
__global__ void __launch_bounds__(64)
snn_layer1_kernel(const float* __restrict__ x, const float* __restrict__ W1)
{
    __shared__ __align__(16) ulonglong2 w1t[14 * 32];   // 7KB
    __shared__ __align__(16) float xs[256 * 64];        // 64KB, XOR-swizzled float4s

    const int tid = threadIdx.x;   // 0..63

    // ---- pack W1: w1t[j*32+kk] = { pk2(W1[2j][2kk],W1[2j+1][2kk]),
    //                                pk2(W1[2j][2kk+1],W1[2j+1][2kk+1]) } ----
    for (int idx = tid; idx < 14 * 32; idx += 64) {
        int j = idx >> 5, kk = idx & 31;
        ulonglong2 v;
        v.x = pk2(W1[(2 * j) * DD + 2 * kk],     W1[(2 * j + 1) * DD + 2 * kk]);
        v.y = pk2(W1[(2 * j) * DD + 2 * kk + 1], W1[(2 * j + 1) * DD + 2 * kk + 1]);
        w1t[idx] = v;
    }

    // ---- stage this block's 256 x rows (contiguous 64KB), swizzled ----
    // physical float4 slot within row = col4 ^ (row & 7)
    const float4* xg = (const float4*)(x + (size_t)blockIdx.x * (256 * DD));
    #pragma unroll
    for (int r = 0; r < 64; r++) {
        int pos  = tid + 64 * r;             // float4 index in 4096-float4 tile
        float4 v = __ldcs(xg + pos);
        int row  = pos >> 4;                 // 0..255
        int col4 = pos & 15;                 // 0..15
        int c4p  = col4 ^ (row & 7);
        ((float4*)(xs + row * 64))[c4p] = v;
    }
    __syncthreads();

    // ---- 4 x 14 serial ascending-k fma2 chains ----
    ull_t acc[4][14];
    #pragma unroll
    for (int u = 0; u < 4; u++)
        #pragma unroll
        for (int j = 0; j < 14; j++) acc[u][j] = 0ULL;

    #pragma unroll 1
    for (int kb = 0; kb < 16; kb++) {        // 4 k per iteration
        // x: one LDS.128 per element (4 k's worth)
        float4 xv[4];
        #pragma unroll
        for (int u = 0; u < 4; u++) {
            int row = tid + 64 * u;
            xv[u] = ((const float4*)(xs + row * 64))[kb ^ (row & 7)];
        }

        #pragma unroll
        for (int half = 0; half < 2; half++) {   // k = 4kb+2half+{0,1}
            ulonglong2 wt[7];
            #pragma unroll
            for (int j2 = 0; j2 < 7; j2++)       // load pairs 0..6 then reuse for 7..13
                wt[j2] = w1t[(2 * j2) * 32 + kb * 2 + half];
            #pragma unroll
            for (int u = 0; u < 4; u++) {
                float x0 = half ? xv[u].z : xv[u].x;
                float x1 = half ? xv[u].w : xv[u].y;
                ull_t xx0 = pk2(x0, x0), xx1 = pk2(x1, x1);
                #pragma unroll
                for (int j2 = 0; j2 < 7; j2++) {
                    acc[u][2 * j2] = fma2(xx1, wt[j2].y, fma2(xx0, wt[j2].x, acc[u][2 * j2]));
                }
            }
            #pragma unroll
            for (int j2 = 0; j2 < 7; j2++)
                wt[j2] = w1t[(2 * j2 + 1) * 32 + kb * 2 + half];
            #pragma unroll
            for (int u = 0; u < 4; u++) {
                float x0 = half ? xv[u].z : xv[u].x;
                float x1 = half ? xv[u].w : xv[u].y;
                ull_t xx0 = pk2(x0, x0), xx1 = pk2(x1, x1);
                #pragma unroll
                for (int j2 = 0; j2 < 7; j2++) {
                    acc[u][2 * j2 + 1] = fma2(xx1, wt[j2].y, fma2(xx0, wt[j2].x, acc[u][2 * j2 + 1]));
                }
            }
        }
    }

    // ---- store to scratch [et][16]: slots 0..6 = pairs 0..6 (q=0 half),
    //      slots 8..14 = pairs 7..13 (q=1 half); aligned STG.128 ----
    #pragma unroll
    for (int u = 0; u < 4; u++) {
        const size_t et = (size_t)blockIdx.x * 256 + tid + 64 * u;
        ulonglong2* d = (ulonglong2*)(g_cur1 + et * 16);
        ulonglong2 p;
        p.x = acc[u][0];  p.y = acc[u][1];  d[0] = p;
        p.x = acc[u][2];  p.y = acc[u][3];  d[1] = p;
        p.x = acc[u][4];  p.y = acc[u][5];  d[2] = p;
        p.x = acc[u][6];  p.y = 0ULL;       d[3] = p;
        p.x = acc[u][7];  p.y = acc[u][8];  d[4] = p;
        p.x = acc[u][9];  p.y = acc[u][10]; d[5] = p;
        p.x = acc[u][11]; p.y = acc[u][12]; d[6] = p;
        p.x = acc[u][13]; p.y = 0ULL;       d[7] = p;
    }
}

// ============================================================================
// Kernel 2: LIF recurrence (r11, UNCHANGED — measured 133-144us).
// ============================================================================
__global__ void __launch_bounds__(64, 1)
snn_recur_kernel(const float* __restrict__ b1,
                 const float* __restrict__ W2, const float* __restrict__ b2,
                 const float* __restrict__ W3, const float* __restrict__ b3,
                 float* __restrict__ out)
{
    __shared__ __align__(16) ull_t w2p[HH1 * 8];
    __shared__ ull_t b1p[14];
    __shared__ ull_t b2p[8];
    __shared__ float w3s[14];
    __shared__ float b3s;

    const int tid  = threadIdx.x;
    const int lane = tid & 31;
    const int warp = tid >> 5;
    const int p    = lane >> 1;            // element slot within warp (0..15)
    const int q    = lane & 1;             // neuron-half owner
    const int e    = blockIdx.x * 32 + warp * 16 + p;

    for (int idx = tid; idx < HH1 * 8; idx += 64) {
        int i = idx >> 3, r = idx & 7, qq = r >> 2, m = r & 3;
        float lo = (2 * m     < 7) ? W2[(qq * 7 + 2 * m)     * HH1 + i] : 0.f;
        float hi = (2 * m + 1 < 7) ? W2[(qq * 7 + 2 * m + 1) * HH1 + i] : 0.f;
        w2p[idx] = pk2(lo, hi);
    }
    if (tid < 14) {
        int qq = tid / 7, ii = tid - qq * 7;
        b1p[tid] = pk2(b1[qq * 14 + 2 * ii], b1[qq * 14 + 2 * ii + 1]);
        w3s[tid] = W3[tid];
    }
    if (tid < 8) {
        int qq = tid >> 2, m = tid & 3;
        float lo = (2 * m     < 7) ? b2[qq * 7 + 2 * m]     : 0.f;
        float hi = (2 * m + 1 < 7) ? b2[qq * 7 + 2 * m + 1] : 0.f;
        b2p[tid] = pk2(lo, hi);
    }
    if (tid == 0) b3s = b3[0];
    __syncthreads();

    ull_t b1own[7], b2own[4];
    #pragma unroll
    for (int i = 0; i < 7; i++) b1own[i] = b1p[q * 7 + i];
    #pragma unroll
    for (int m = 0; m < 4; m++) b2own[m] = b2p[q * 4 + m];

    const ull_t BETA2 = pk2(0.9f, 0.9f);
    const ull_t NEG2  = pk2(-1.0f, -1.0f);

    ull_t m1v[7], m2v[4];
    #pragma unroll
    for (int i = 0; i < 7; i++) m1v[i] = 0ULL;
    #pragma unroll
    for (int m = 0; m < 4; m++) m2v[m] = 0ULL;
    float m3 = 0.0f;

    const ull_t* cbase = g_cur1 + (size_t)e * 16 + q * 8;
    const size_t cstep = (size_t)BB * 16;

    // ---- preload acc for t=0 ----
    ulonglong2 c0, c1, c2, c3v;
    {
        const ulonglong2* cp = (const ulonglong2*)cbase;
        c0 = cp[0]; c1 = cp[1]; c2 = cp[2]; c3v = cp[3];
    }

    #pragma unroll 1
    for (int t = 0; t < TT; t++) {
        // ---- issue next step's acc loads NOW (consumed next iteration) ----
        const int tn = (t + 1 < TT) ? (t + 1) : t;
        const ulonglong2* np = (const ulonglong2*)(cbase + (size_t)tn * cstep);
        ulonglong2 n0 = np[0], n1 = np[1], n2 = np[2], n3 = np[3];

        // ---- prefetch t+2 into L2 so next iteration's LDG is an L2 hit ----
        if (t + 2 < TT) {
            const char* pf = (const char*)(cbase + (size_t)(t + 2) * cstep);
            asm volatile("prefetch.global.L2 [%0];" :: "l"(pf));
        }

        ull_t acc[7] = {c0.x, c0.y, c1.x, c1.y, c2.x, c2.y, c3v.x};

        // ---- LIF layer 1 (exact rounding sequence) ----
        float s1own[14];
        #pragma unroll
        for (int i = 0; i < 7; i++) {
            ull_t mold = m1v[i];
            float mlo, mhi;
            upk2(mold, mlo, mhi);
            float rlo = (mlo > 1.0f) ? 1.0f : 0.0f;
            float rhi = (mhi > 1.0f) ? 1.0f : 0.0f;
            ull_t cur = add2(acc[i], b1own[i]);
            ull_t mb  = mul2(BETA2, mold);
            ull_t tmp = add2(mb, cur);
            ull_t mn  = fma2(pk2(rlo, rhi), NEG2, tmp);
            m1v[i] = mn;
            float nlo, nhi;
            upk2(mn, nlo, nhi);
            s1own[2 * i]     = (nlo > 1.0f) ? 1.0f : 0.0f;
            s1own[2 * i + 1] = (nhi > 1.0f) ? 1.0f : 0.0f;
        }

        // ---- exchange spike halves across the pair ----
        float s1o[14];
        #pragma unroll
        for (int i = 0; i < 7; i++) {
            ull_t sp = pk2(s1own[2 * i], s1own[2 * i + 1]);
            ull_t g  = __shfl_xor_sync(0xFFFFFFFFu, sp, 1);
            upk2(g, s1o[2 * i], s1o[2 * i + 1]);
        }
        float s1all[28];
        #pragma unroll
        for (int i = 0; i < 14; i++) {
            s1all[i]      = q ? s1o[i]   : s1own[i];
            s1all[14 + i] = q ? s1own[i] : s1o[i];
        }

        // ---- layer 2: serial ascending-i FMA chains ----
        ull_t a2[4];
        #pragma unroll
        for (int m = 0; m < 4; m++) a2[m] = 0ULL;
        #pragma unroll
        for (int i = 0; i < HH1; i++) {
            ull_t ss = pk2(s1all[i], s1all[i]);
            const ulonglong2* wr = (const ulonglong2*)(w2p + (size_t)i * 8 + q * 4);
            ulonglong2 u0 = wr[0], u1 = wr[1];
            a2[0] = fma2(ss, u0.x, a2[0]);
            a2[1] = fma2(ss, u0.y, a2[1]);
            a2[2] = fma2(ss, u1.x, a2[2]);
            a2[3] = fma2(ss, u1.y, a2[3]);
        }

        // ---- LIF layer 2 ----
        float s2own[8];
        #pragma unroll
        for (int m = 0; m < 4; m++) {
            ull_t mold = m2v[m];
            float mlo, mhi;
            upk2(mold, mlo, mhi);
            float rlo = (mlo > 1.0f) ? 1.0f : 0.0f;
            float rhi = (mhi > 1.0f) ? 1.0f : 0.0f;
            ull_t cur = add2(a2[m], b2own[m]);
            ull_t mb  = mul2(BETA2, mold);
            ull_t tmp = add2(mb, cur);
            ull_t mn  = fma2(pk2(rlo, rhi), NEG2, tmp);
            m2v[m] = mn;
            float nlo, nhi;
            upk2(mn, nlo, nhi);
            s2own[2 * m]     = (nlo > 1.0f) ? 1.0f : 0.0f;
            s2own[2 * m + 1] = (nhi > 1.0f) ? 1.0f : 0.0f;
        }

        // ---- exchange s2 halves ----
        float s2o[8];
        #pragma unroll
        for (int m = 0; m < 4; m++) {
            ull_t sp = pk2(s2own[2 * m], s2own[2 * m + 1]);
            ull_t g  = __shfl_xor_sync(0xFFFFFFFFu, sp, 1);
            upk2(g, s2o[2 * m], s2o[2 * m + 1]);
        }
        float s2all[14];
        #pragma unroll
        for (int i = 0; i < 7; i++) {
            s2all[i]     = q ? s2o[i]   : s2own[i];
            s2all[7 + i] = q ? s2own[i] : s2o[i];
        }

        // ---- layer 3 + LIF 3 ----
        float c3 = 0.0f;
        #pragma unroll
        for (int i = 0; i < HH2; i++) c3 = fmaf(s2all[i], w3s[i], c3);
        float cur3 = __fadd_rn(c3, b3s);

        float r3  = (m3 > 1.0f) ? 1.0f : 0.0f;
        float mb3 = __fmul_rn(0.9f, m3);
        float t3  = __fadd_rn(mb3, cur3);
        m3 = __fsub_rn(t3, r3);

        if (q == 0) out[(size_t)t * BB + e] = m3;

        // ---- rotate double-buffered acc ----
        c0 = n0; c1 = n1; c2 = n2; c3v = n3;
    }
}

extern "C" void kernel_launch(void* const* d_in, const int* in_sizes, int n_in,
                              void* d_out, int out_size) {
    const float* x  = (const float*)d_in[0];
    const float* W1 = (const float*)d_in[1];
    const float* b1 = (const float*)d_in[2];
    const float* W2 = (const float*)d_in[3];
    const float* b2 = (const float*)d_in[4];
    const float* W3 = (const float*)d_in[5];
    const float* b3 = (const float*)d_in[6];
    float* out = (float*)d_out;

    // K1: 2,097,152 element-timesteps, 4 per thread -> 8192 blocks x 64
    snn_layer1_kernel<<<8192, 64>>>(x, W1);

    // K2: 8192 elements, 32 per block (64 threads = 2 threads per element)
    snn_recur_kernel<<<256, 64>>>(b1, W2, b2, W3, b3, out);
}

// round 16
// speedup vs baseline: 1.6802x; 1.0369x over previous
#include <cuda_runtime.h>

// EthanolSNN: 3-layer LIF SNN inference. T=256, B=8192, D=64, H1=28, H2=14.
// Output mem3 [T, B, 1] fp32.
//
// Two-kernel split:
//  K1 (r15): layer-1 accumulations with PAIR NEURON-SPLIT: even/odd lanes of
//      a thread-pair own h1-pair halves (0-6 / 7-13), 8 elements per pair.
//      One weight LDS.128 set (7 per 2k) now feeds 8 elements x 14 neurons
//      (r14: 14 LDS per 2k for 4 elements) -> warp LDS.128 count 512 -> 352,
//      crossbar (4cyc/LDS.128) drops below the fma2 floor.
//  K2: sequential LIF recurrence with register double-buffered acc loads
//      (UNCHANGED from r11, measured 133-144us across 4 rounds).
//
// Numerics BIT-IDENTICAL to round-5 passing kernel (rel_err 7.44e-4):
//  - dot products: single serial ascending-index FMA chain per neuron
//  - bias added as separate rounded add after the chain
//  - LIF: RN(RN(RN(b*m)+cur)-reset), reset subtract via exact-product fma
//  - threshold m>1 == (m-1)>0 in fp32

typedef unsigned long long ull_t;

#define TT 256
#define BB 8192
#define DD 64
#define HH1 28
#define HH2 14

// scratch: [et][16] ull; et = t*BB+e; half q uses slots [q*8 .. q*8+6]
#define SCRATCH_ULLS (256ULL * 8192ULL * 16ULL)
__device__ ull_t g_cur1[SCRATCH_ULLS];   // 268 MB, module-load allocated

__device__ __forceinline__ ull_t pk2(float lo, float hi) {
    ull_t r;
    asm("mov.b64 %0, {%1, %2};" : "=l"(r) : "f"(lo), "f"(hi));
    return r;
}
__device__ __forceinline__ void upk2(ull_t v, float& lo, float& hi) {
    asm("mov.b64 {%0, %1}, %2;" : "=f"(lo), "=f"(hi) : "l"(v));
}
__device__ __forceinline__ ull_t fma2(ull_t a, ull_t b, ull_t c) {
    ull_t d;
    asm("fma.rn.f32x2 %0, %1, %2, %3;" : "=l"(d) : "l"(a), "l"(b), "l"(c));
    return d;
}
__device__ __forceinline__ ull_t add2(ull_t a, ull_t b) {
    ull_t d;
    asm("add.rn.f32x2 %0, %1, %2;" : "=l"(d) : "l"(a), "l"(b));
    return d;
}
__device__ __forceinline__ ull_t mul2(ull_t a, ull_t b) {
    ull_t d;
    asm("mul.rn.f32x2 %0, %1, %2;" : "=l"(d) : "l"(a), "l"(b));
    return d;
}

// ============================================================================
// Kernel 1 (r15): layer-1 accumulation, pair neuron-split, 8 elements/pair.
// Block = 64 threads = 32 pairs... actually 16 pairs/warp x 2 warps; pair
// P = w*16 + (lane>>1) owns elements (rows) P + 32u, u=0..7; lane q = lane&1
// owns h1 pairs q*7 .. q*7+6.
//  - w1t[j*32+kk] (ulonglong2): h1-pair j, k=2kk,2kk+1 packed
//  - per 2k: 7 weight LDS.128 (even/odd lanes fetch their half's rows)
//  - x tile: 256 rows x 64 floats, float4 slots XOR-swizzled by (row&7);
//    one x LDS.128 per element per 4k, pair lanes broadcast the same address
// 8 x 7 serial ascending-k fma2 chains per thread (bit-identical numerics).
// ============================================================================
__global__ void __launch_bounds__(64)
snn_layer1_kernel(const float* __restrict__ x, const float* __restrict__ W1)
{
    __shared__ __align__(16) ulonglong2 w1t[14 * 32];   // 7KB
    __shared__ __align__(16) float xs[256 * 64];        // 64KB, XOR-swizzled float4s

    const int tid  = threadIdx.x;   // 0..63
    const int lane = tid & 31;
    const int q    = lane & 1;                   // neuron-half owner
    const int P    = (tid >> 5) * 16 + (lane >> 1);   // pair index 0..31

    // ---- pack W1: w1t[j*32+kk] = { pk2(W1[2j][2kk],W1[2j+1][2kk]),
    //                                pk2(W1[2j][2kk+1],W1[2j+1][2kk+1]) } ----
    for (int idx = tid; idx < 14 * 32; idx += 64) {
        int j = idx >> 5, kk = idx & 31;
        ulonglong2 v;
        v.x = pk2(W1[(2 * j) * DD + 2 * kk],     W1[(2 * j + 1) * DD + 2 * kk]);
        v.y = pk2(W1[(2 * j) * DD + 2 * kk + 1], W1[(2 * j + 1) * DD + 2 * kk + 1]);
        w1t[idx] = v;
    }

    // ---- stage this block's 256 x rows (contiguous 64KB), swizzled ----
    const float4* xg = (const float4*)(x + (size_t)blockIdx.x * (256 * DD));
    #pragma unroll
    for (int r = 0; r < 64; r++) {
        int pos  = tid + 64 * r;             // float4 index in 4096-float4 tile
        float4 v = __ldcs(xg + pos);
        int row  = pos >> 4;                 // 0..255
        int col4 = pos & 15;                 // 0..15
        int c4p  = col4 ^ (row & 7);
        ((float4*)(xs + row * 64))[c4p] = v;
    }
    __syncthreads();

    // ---- 8 x 7 serial ascending-k fma2 chains (this thread's neuron half) ----
    ull_t acc[8][7];
    #pragma unroll
    for (int u = 0; u < 8; u++)
        #pragma unroll
        for (int j = 0; j < 7; j++) acc[u][j] = 0ULL;

    const int jbase = q * 7;   // this thread's h1 pairs: jbase .. jbase+6

    #pragma unroll 1
    for (int kb = 0; kb < 16; kb++) {        // 4 k per iteration
        // x: one LDS.128 per element (4 k's worth); pair lanes share address
        float4 xv[8];
        #pragma unroll
        for (int u = 0; u < 8; u++) {
            int row = P + 32 * u;
            xv[u] = ((const float4*)(xs + row * 64))[kb ^ (row & 7)];
        }

        #pragma unroll
        for (int half = 0; half < 2; half++) {   // k = 4kb+2half+{0,1}
            ulonglong2 wt[7];
            #pragma unroll
            for (int j2 = 0; j2 < 7; j2++)
                wt[j2] = w1t[(jbase + j2) * 32 + kb * 2 + half];
            #pragma unroll
            for (int u = 0; u < 8; u++) {
                float x0 = half ? xv[u].z : xv[u].x;
                float x1 = half ? xv[u].w : xv[u].y;
                ull_t xx0 = pk2(x0, x0), xx1 = pk2(x1, x1);
                #pragma unroll
                for (int j2 = 0; j2 < 7; j2++) {
                    acc[u][j2] = fma2(xx1, wt[j2].y, fma2(xx0, wt[j2].x, acc[u][j2]));
                }
            }
        }
    }

    // ---- store to scratch [et][16]: thread half q writes slots q*8..q*8+6
    //      (pair lanes together cover 256B per et, coalesced) ----
    #pragma unroll
    for (int u = 0; u < 8; u++) {
        const size_t et = (size_t)blockIdx.x * 256 + P + 32 * u;
        ulonglong2* d = (ulonglong2*)(g_cur1 + et * 16 + q * 8);
        ulonglong2 p;
        p.x = acc[u][0]; p.y = acc[u][1]; d[0] = p;
        p.x = acc[u][2]; p.y = acc[u][3]; d[1] = p;
        p.x = acc[u][4]; p.y = acc[u][5]; d[2] = p;
        p.x = acc[u][6]; p.y = 0ULL;      d[3] = p;
    }
}

// ============================================================================
// Kernel 2: LIF recurrence (r11, UNCHANGED — measured 133-144us).
// ============================================================================
__global__ void __launch_bounds__(64, 1)
snn_recur_kernel(const float* __restrict__ b1,
                 const float* __restrict__ W2, const float* __restrict__ b2,
                 const float* __restrict__ W3, const float* __restrict__ b3,
                 float* __restrict__ out)
{
    __shared__ __align__(16) ull_t w2p[HH1 * 8];
    __shared__ ull_t b1p[14];
    __shared__ ull_t b2p[8];
    __shared__ float w3s[14];
    __shared__ float b3s;

    const int tid  = threadIdx.x;
    const int lane = tid & 31;
    const int warp = tid >> 5;
    const int p    = lane >> 1;            // element slot within warp (0..15)
    const int q    = lane & 1;             // neuron-half owner
    const int e    = blockIdx.x * 32 + warp * 16 + p;

    for (int idx = tid; idx < HH1 * 8; idx += 64) {
        int i = idx >> 3, r = idx & 7, qq = r >> 2, m = r & 3;
        float lo = (2 * m     < 7) ? W2[(qq * 7 + 2 * m)     * HH1 + i] : 0.f;
        float hi = (2 * m + 1 < 7) ? W2[(qq * 7 + 2 * m + 1) * HH1 + i] : 0.f;
        w2p[idx] = pk2(lo, hi);
    }
    if (tid < 14) {
        int qq = tid / 7, ii = tid - qq * 7;
        b1p[tid] = pk2(b1[qq * 14 + 2 * ii], b1[qq * 14 + 2 * ii + 1]);
        w3s[tid] = W3[tid];
    }
    if (tid < 8) {
        int qq = tid >> 2, m = tid & 3;
        float lo = (2 * m     < 7) ? b2[qq * 7 + 2 * m]     : 0.f;
        float hi = (2 * m + 1 < 7) ? b2[qq * 7 + 2 * m + 1] : 0.f;
        b2p[tid] = pk2(lo, hi);
    }
    if (tid == 0) b3s = b3[0];
    __syncthreads();

    ull_t b1own[7], b2own[4];
    #pragma unroll
    for (int i = 0; i < 7; i++) b1own[i] = b1p[q * 7 + i];
    #pragma unroll
    for (int m = 0; m < 4; m++) b2own[m] = b2p[q * 4 + m];

    const ull_t BETA2 = pk2(0.9f, 0.9f);
    const ull_t NEG2  = pk2(-1.0f, -1.0f);

    ull_t m1v[7], m2v[4];
    #pragma unroll
    for (int i = 0; i < 7; i++) m1v[i] = 0ULL;
    #pragma unroll
    for (int m = 0; m < 4; m++) m2v[m] = 0ULL;
    float m3 = 0.0f;

    const ull_t* cbase = g_cur1 + (size_t)e * 16 + q * 8;
    const size_t cstep = (size_t)BB * 16;

    // ---- preload acc for t=0 ----
    ulonglong2 c0, c1, c2, c3v;
    {
        const ulonglong2* cp = (const ulonglong2*)cbase;
        c0 = cp[0]; c1 = cp[1]; c2 = cp[2]; c3v = cp[3];
    }

    #pragma unroll 1
    for (int t = 0; t < TT; t++) {
        // ---- issue next step's acc loads NOW (consumed next iteration) ----
        const int tn = (t + 1 < TT) ? (t + 1) : t;
        const ulonglong2* np = (const ulonglong2*)(cbase + (size_t)tn * cstep);
        ulonglong2 n0 = np[0], n1 = np[1], n2 = np[2], n3 = np[3];

        // ---- prefetch t+2 into L2 so next iteration's LDG is an L2 hit ----
        if (t + 2 < TT) {
            const char* pf = (const char*)(cbase + (size_t)(t + 2) * cstep);
            asm volatile("prefetch.global.L2 [%0];" :: "l"(pf));
        }

        ull_t acc[7] = {c0.x, c0.y, c1.x, c1.y, c2.x, c2.y, c3v.x};

        // ---- LIF layer 1 (exact rounding sequence) ----
        float s1own[14];
        #pragma unroll
        for (int i = 0; i < 7; i++) {
            ull_t mold = m1v[i];
            float mlo, mhi;
            upk2(mold, mlo, mhi);
            float rlo = (mlo > 1.0f) ? 1.0f : 0.0f;
            float rhi = (mhi > 1.0f) ? 1.0f : 0.0f;
            ull_t cur = add2(acc[i], b1own[i]);
            ull_t mb  = mul2(BETA2, mold);
            ull_t tmp = add2(mb, cur);
            ull_t mn  = fma2(pk2(rlo, rhi), NEG2, tmp);
            m1v[i] = mn;
            float nlo, nhi;
            upk2(mn, nlo, nhi);
            s1own[2 * i]     = (nlo > 1.0f) ? 1.0f : 0.0f;
            s1own[2 * i + 1] = (nhi > 1.0f) ? 1.0f : 0.0f;
        }

        // ---- exchange spike halves across the pair ----
        float s1o[14];
        #pragma unroll
        for (int i = 0; i < 7; i++) {
            ull_t sp = pk2(s1own[2 * i], s1own[2 * i + 1]);
            ull_t g  = __shfl_xor_sync(0xFFFFFFFFu, sp, 1);
            upk2(g, s1o[2 * i], s1o[2 * i + 1]);
        }
        float s1all[28];
        #pragma unroll
        for (int i = 0; i < 14; i++) {
            s1all[i]      = q ? s1o[i]   : s1own[i];
            s1all[14 + i] = q ? s1own[i] : s1o[i];
        }

        // ---- layer 2: serial ascending-i FMA chains ----
        ull_t a2[4];
        #pragma unroll
        for (int m = 0; m < 4; m++) a2[m] = 0ULL;
        #pragma unroll
        for (int i = 0; i < HH1; i++) {
            ull_t ss = pk2(s1all[i], s1all[i]);
            const ulonglong2* wr = (const ulonglong2*)(w2p + (size_t)i * 8 + q * 4);
            ulonglong2 u0 = wr[0], u1 = wr[1];
            a2[0] = fma2(ss, u0.x, a2[0]);
            a2[1] = fma2(ss, u0.y, a2[1]);
            a2[2] = fma2(ss, u1.x, a2[2]);
            a2[3] = fma2(ss, u1.y, a2[3]);
        }

        // ---- LIF layer 2 ----
        float s2own[8];
        #pragma unroll
        for (int m = 0; m < 4; m++) {
            ull_t mold = m2v[m];
            float mlo, mhi;
            upk2(mold, mlo, mhi);
            float rlo = (mlo > 1.0f) ? 1.0f : 0.0f;
            float rhi = (mhi > 1.0f) ? 1.0f : 0.0f;
            ull_t cur = add2(a2[m], b2own[m]);
            ull_t mb  = mul2(BETA2, mold);
            ull_t tmp = add2(mb, cur);
            ull_t mn  = fma2(pk2(rlo, rhi), NEG2, tmp);
            m2v[m] = mn;
            float nlo, nhi;
            upk2(mn, nlo, nhi);
            s2own[2 * m]     = (nlo > 1.0f) ? 1.0f : 0.0f;
            s2own[2 * m + 1] = (nhi > 1.0f) ? 1.0f : 0.0f;
        }

        // ---- exchange s2 halves ----
        float s2o[8];
        #pragma unroll
        for (int m = 0; m < 4; m++) {
            ull_t sp = pk2(s2own[2 * m], s2own[2 * m + 1]);
            ull_t g  = __shfl_xor_sync(0xFFFFFFFFu, sp, 1);
            upk2(g, s2o[2 * m], s2o[2 * m + 1]);
        }
        float s2all[14];
        #pragma unroll
        for (int i = 0; i < 7; i++) {
            s2all[i]     = q ? s2o[i]   : s2own[i];
            s2all[7 + i] = q ? s2own[i] : s2o[i];
        }

        // ---- layer 3 + LIF 3 ----
        float c3 = 0.0f;
        #pragma unroll
        for (int i = 0; i < HH2; i++) c3 = fmaf(s2all[i], w3s[i], c3);
        float cur3 = __fadd_rn(c3, b3s);

        float r3  = (m3 > 1.0f) ? 1.0f : 0.0f;
        float mb3 = __fmul_rn(0.9f, m3);
        float t3  = __fadd_rn(mb3, cur3);
        m3 = __fsub_rn(t3, r3);

        if (q == 0) out[(size_t)t * BB + e] = m3;

        // ---- rotate double-buffered acc ----
        c0 = n0; c1 = n1; c2 = n2; c3v = n3;
    }
}

extern "C" void kernel_launch(void* const* d_in, const int* in_sizes, int n_in,
                              void* d_out, int out_size) {
    const float* x  = (const float*)d_in[0];
    const float* W1 = (const float*)d_in[1];
    const float* b1 = (const float*)d_in[2];
    const float* W2 = (const float*)d_in[3];
    const float* b2 = (const float*)d_in[4];
    const float* W3 = (const float*)d_in[5];
    const float* b3 = (const float*)d_in[6];
    float* out = (float*)d_out;

    // K1: 2,097,152 element-timesteps; 32 pairs x 8 elements per 64-thr block
    // -> 8192 blocks x 64
    snn_layer1_kernel<<<8192, 64>>>(x, W1);

    // K2: 8192 elements, 32 per block (64 threads = 2 threads per element)
    snn_recur_kernel<<<256, 64>>>(b1, W2, b2, W3, b3, out);
}